// round 2
// baseline (speedup 1.0000x reference)
#include <cuda_runtime.h>
#include <math.h>

// Problem dimensions (fixed by the reference)
#define BATCH 8192
#define PDIM  512
#define H1DIM 1024
#define H2DIM 512
#define NOUTD 1024
#define MMDIM 512
#define NCODE 2048
#define KSTEPS 16

// ---------------- scratch (device globals; no allocations allowed) ----------
__device__ float g_h1[(size_t)BATCH * H1DIM];        // MLP hidden 1
__device__ float g_h2[(size_t)BATCH * H2DIM];        // MLP hidden 2, reused as r [B, Mm]
__device__ float g_v [(size_t)BATCH * NCODE];        // FISTA extrapolation point
__device__ float g_a0[(size_t)BATCH * NCODE];        // alpha ping
__device__ float g_a1[(size_t)BATCH * NCODE];        // alpha pong

enum { EPI_GELU = 0, EPI_BIAS, EPI_ZSUB, EPI_RSUB, EPI_FISTA, EPI_ADD };

__device__ __forceinline__ float gelu_exact(float x) {
    // jax.nn.gelu(approximate=False) = 0.5*x*(1+erf(x/sqrt(2)))
    return 0.5f * x * (1.0f + erff(x * 0.70710678118654752440f));
}

// ---------------------------------------------------------------------------
// Tiled fp32 GEMM: C[M,N] = A[M,K] * B, 128x128 tile, BK=16, 256 threads,
// double-buffered SMEM, 8x8 per-thread microtile. BT=false: B is [K,N]
// row-major.  BT=true: B is [N,K] row-major (i.e. compute A*B^T).
// M, N multiples of 128; K multiple of 16 (guaranteed by problem shapes).
// ---------------------------------------------------------------------------
template <int EPI, bool BT>
__global__ void __launch_bounds__(256)
gemm128(const float* __restrict__ Ag, const float* __restrict__ Bg,
        float* __restrict__ Cg, int Ndim, int Kdim,
        const float* __restrict__ aux,        // bias [N] or matrix [M,N] per EPI
        const float* __restrict__ log_eta,
        const float* __restrict__ log_tau, int kidx)
{
    __shared__ float As[2][16][128];
    __shared__ float Bs[2][16][128];

    const int tid = threadIdx.x;
    const int tx  = tid & 15;     // 0..15 : 8-col group
    const int ty  = tid >> 4;     // 0..15 : 8-row group
    const int m0  = blockIdx.y * 128;
    const int n0  = blockIdx.x * 128;

    // loader indices
    const int lr = tid >> 2;      // 0..63  (row, A and B-NT)
    const int lc = tid & 3;       // 0..3   (float4 slot along K)
    const int br = tid >> 5;      // 0..7   (k-row, B-NN)
    const int bc = tid & 31;      // 0..31  (float4 slot along N)

    float acc[8][8];
#pragma unroll
    for (int i = 0; i < 8; i++)
#pragma unroll
        for (int j = 0; j < 8; j++) acc[i][j] = 0.0f;

    const int nk = Kdim >> 4;

    // ---- preload tile 0 -----------------------------------------------------
    {
        float4 a0 = *(const float4*)&Ag[(size_t)(m0 + lr) * Kdim + lc * 4];
        float4 a1 = *(const float4*)&Ag[(size_t)(m0 + lr + 64) * Kdim + lc * 4];
#pragma unroll
        for (int j = 0; j < 4; j++) {
            As[0][lc * 4 + j][lr]      = ((const float*)&a0)[j];
            As[0][lc * 4 + j][lr + 64] = ((const float*)&a1)[j];
        }
        if (BT) {
            float4 b0 = *(const float4*)&Bg[(size_t)(n0 + lr) * Kdim + lc * 4];
            float4 b1 = *(const float4*)&Bg[(size_t)(n0 + lr + 64) * Kdim + lc * 4];
#pragma unroll
            for (int j = 0; j < 4; j++) {
                Bs[0][lc * 4 + j][lr]      = ((const float*)&b0)[j];
                Bs[0][lc * 4 + j][lr + 64] = ((const float*)&b1)[j];
            }
        } else {
            float4 b0 = *(const float4*)&Bg[(size_t)br * Ndim + n0 + bc * 4];
            float4 b1 = *(const float4*)&Bg[(size_t)(br + 8) * Ndim + n0 + bc * 4];
            *(float4*)&Bs[0][br][bc * 4]     = b0;
            *(float4*)&Bs[0][br + 8][bc * 4] = b1;
        }
    }
    __syncthreads();

    int buf = 0;
    for (int kt = 0; kt < nk; kt++) {
        float4 pa0, pa1, pb0, pb1;
        const bool more = (kt + 1 < nk);
        if (more) {   // issue next-tile global loads early; latency hides under FMAs
            const int ko = (kt + 1) * 16;
            pa0 = *(const float4*)&Ag[(size_t)(m0 + lr) * Kdim + ko + lc * 4];
            pa1 = *(const float4*)&Ag[(size_t)(m0 + lr + 64) * Kdim + ko + lc * 4];
            if (BT) {
                pb0 = *(const float4*)&Bg[(size_t)(n0 + lr) * Kdim + ko + lc * 4];
                pb1 = *(const float4*)&Bg[(size_t)(n0 + lr + 64) * Kdim + ko + lc * 4];
            } else {
                pb0 = *(const float4*)&Bg[(size_t)(ko + br) * Ndim + n0 + bc * 4];
                pb1 = *(const float4*)&Bg[(size_t)(ko + br + 8) * Ndim + n0 + bc * 4];
            }
        }
#pragma unroll
        for (int k = 0; k < 16; k++) {
            float4 av0 = *(const float4*)&As[buf][k][ty * 8];
            float4 av1 = *(const float4*)&As[buf][k][ty * 8 + 4];
            float4 bv0 = *(const float4*)&Bs[buf][k][tx * 8];
            float4 bv1 = *(const float4*)&Bs[buf][k][tx * 8 + 4];
            float a[8] = {av0.x, av0.y, av0.z, av0.w, av1.x, av1.y, av1.z, av1.w};
            float b[8] = {bv0.x, bv0.y, bv0.z, bv0.w, bv1.x, bv1.y, bv1.z, bv1.w};
#pragma unroll
            for (int i = 0; i < 8; i++)
#pragma unroll
                for (int j = 0; j < 8; j++)
                    acc[i][j] = fmaf(a[i], b[j], acc[i][j]);
        }
        if (more) {
            const int nb = buf ^ 1;
#pragma unroll
            for (int j = 0; j < 4; j++) {
                As[nb][lc * 4 + j][lr]      = ((const float*)&pa0)[j];
                As[nb][lc * 4 + j][lr + 64] = ((const float*)&pa1)[j];
            }
            if (BT) {
#pragma unroll
                for (int j = 0; j < 4; j++) {
                    Bs[nb][lc * 4 + j][lr]      = ((const float*)&pb0)[j];
                    Bs[nb][lc * 4 + j][lr + 64] = ((const float*)&pb1)[j];
                }
            } else {
                *(float4*)&Bs[nb][br][bc * 4]     = pb0;
                *(float4*)&Bs[nb][br + 8][bc * 4] = pb1;
            }
            __syncthreads();
            buf = nb;
        }
    }

    // ---- fused epilogue -----------------------------------------------------
    float eta = 0.0f, thr = 0.0f;
    if (EPI == EPI_FISTA) {
        eta = expf(log_eta[kidx]);
        eta = fminf(fmaxf(eta, 1e-8f), 10.0f);
        float tau = expf(log_tau[kidx]);
        tau = fminf(fmaxf(tau, 1e-8f), 10.0f);
        thr = eta * tau;
    }
    const int cm = m0 + ty * 8;
    const int cn = n0 + tx * 8;
#pragma unroll
    for (int i = 0; i < 8; i++) {
#pragma unroll
        for (int j = 0; j < 8; j++) {
            float r = acc[i][j];
            float o;
            if (EPI == EPI_GELU) {
                o = gelu_exact(r + aux[cn + j]);
            } else if (EPI == EPI_BIAS) {
                o = r + aux[cn + j];
            } else if (EPI == EPI_ZSUB) {            // z = b - acc
                o = aux[(size_t)(cm + i) * Ndim + cn + j] - r;
            } else if (EPI == EPI_RSUB) {            // r = acc - z
                o = r - aux[(size_t)(cm + i) * Ndim + cn + j];
            } else if (EPI == EPI_FISTA) {           // soft(v - eta*acc, eta*tau)
                float u = aux[(size_t)(cm + i) * Ndim + cn + j] - eta * r;
                o = copysignf(fmaxf(fabsf(u) - thr, 0.0f), u);
            } else {                                 // EPI_ADD: y_hat = y_bg + acc
                o = r + aux[(size_t)(cm + i) * Ndim + cn + j];
            }
            acc[i][j] = o;
        }
        *(float4*)&Cg[(size_t)(cm + i) * Ndim + cn]     = *(float4*)&acc[i][0];
        *(float4*)&Cg[(size_t)(cm + i) * Ndim + cn + 4] = *(float4*)&acc[i][4];
    }
}

// v = alpha + beta*(alpha - alpha_prev), vectorized
__global__ void vcomb_kernel(const float4* __restrict__ a,
                             const float4* __restrict__ ap,
                             float4* __restrict__ v, float beta, int n4)
{
    int i = blockIdx.x * blockDim.x + threadIdx.x;
    if (i < n4) {
        float4 av = a[i], pv = ap[i], o;
        o.x = av.x + beta * (av.x - pv.x);
        o.y = av.y + beta * (av.y - pv.y);
        o.z = av.z + beta * (av.z - pv.z);
        o.w = av.w + beta * (av.w - pv.w);
        v[i] = o;
    }
}

__global__ void fill0_kernel(float4* __restrict__ p, int n4)
{
    int i = blockIdx.x * blockDim.x + threadIdx.x;
    if (i < n4) p[i] = make_float4(0.f, 0.f, 0.f, 0.f);
}

// ---------------------------------------------------------------------------
extern "C" void kernel_launch(void* const* d_in, const int* in_sizes, int n_in,
                              void* d_out, int out_size)
{
    const float* x    = (const float*)d_in[0];
    const float* bvec = (const float*)d_in[1];   // b  [B, Mm]
    const float* W1   = (const float*)d_in[2];
    const float* b1   = (const float*)d_in[3];
    const float* W2   = (const float*)d_in[4];
    const float* b2   = (const float*)d_in[5];
    const float* W3   = (const float*)d_in[6];
    const float* b3   = (const float*)d_in[7];
    const float* A    = (const float*)d_in[8];   // [Mm, NCODE]
    const float* leta = (const float*)d_in[9];
    const float* ltau = (const float*)d_in[10];
    const float* Psi  = (const float*)d_in[11];  // [NOUT, NCODE]
    const float* Mmat = (const float*)d_in[12];  // [Mm, NOUT]

    float* out     = (float*)d_out;
    float* o_ybg   = out;
    float* o_z     = o_ybg + (size_t)BATCH * NOUTD;
    float* o_alpha = o_z   + (size_t)BATCH * MMDIM;
    float* o_yhat  = o_alpha + (size_t)BATCH * NCODE;

    float *h1, *h2, *v, *a0, *a1;
    cudaGetSymbolAddress((void**)&h1, g_h1);
    cudaGetSymbolAddress((void**)&h2, g_h2);
    cudaGetSymbolAddress((void**)&v,  g_v);
    cudaGetSymbolAddress((void**)&a0, g_a0);
    cudaGetSymbolAddress((void**)&a1, g_a1);

    const dim3 blk(256);

    // ---- background MLP -----------------------------------------------------
    gemm128<EPI_GELU, false><<<dim3(H1DIM / 128, BATCH / 128), blk>>>(
        x, W1, h1, H1DIM, PDIM, b1, nullptr, nullptr, 0);
    gemm128<EPI_GELU, false><<<dim3(H2DIM / 128, BATCH / 128), blk>>>(
        h1, W2, h2, H2DIM, H1DIM, b2, nullptr, nullptr, 0);
    gemm128<EPI_BIAS, false><<<dim3(NOUTD / 128, BATCH / 128), blk>>>(
        h2, W3, o_ybg, NOUTD, H2DIM, b3, nullptr, nullptr, 0);

    // ---- z = b - y_bg @ M^T  (M stored [Mm, NOUT] => NT layout) -------------
    gemm128<EPI_ZSUB, true><<<dim3(MMDIM / 128, BATCH / 128), blk>>>(
        o_ybg, Mmat, o_z, MMDIM, NOUTD, bvec, nullptr, nullptr, 0);

    // ---- FISTA loop ----------------------------------------------------------
    const int n4 = (BATCH * NCODE) / 4;
    fill0_kernel<<<(n4 + 255) / 256, 256>>>((float4*)a0, n4);
    fill0_kernel<<<(n4 + 255) / 256, 256>>>((float4*)a1, n4);

    float t = 1.0f;
    float* aprev = a0;
    float* acur  = a1;
    for (int k = 0; k < KSTEPS; k++) {
        float beta = 0.0f;
        if (k > 0) {   // data-independent momentum recurrence (fp32, as in ref)
            float tn = 0.5f * (1.0f + sqrtf(1.0f + 4.0f * t * t));
            beta = (t - 1.0f) / tn;
            t = tn;
        }
        vcomb_kernel<<<(n4 + 255) / 256, 256>>>(
            (const float4*)acur, (const float4*)aprev, (float4*)v, beta, n4);

        // r = v @ A^T - z   (A [Mm, NCODE] => NT, N=Mm, K=NCODE); r lives in g_h2
        gemm128<EPI_RSUB, true><<<dim3(MMDIM / 128, BATCH / 128), blk>>>(
            v, A, h2, MMDIM, NCODE, o_z, nullptr, nullptr, 0);

        // alpha_new = soft(v - eta*(r @ A), eta*tau)   (NN, N=NCODE, K=Mm)
        float* dst = (k == KSTEPS - 1) ? o_alpha : aprev;
        gemm128<EPI_FISTA, false><<<dim3(NCODE / 128, BATCH / 128), blk>>>(
            h2, A, dst, NCODE, MMDIM, v, leta, ltau, k);

        aprev = acur;
        acur  = dst;
    }

    // ---- y_hat = y_bg + alpha @ Psi^T  (Psi [NOUT, NCODE] => NT) ------------
    gemm128<EPI_ADD, true><<<dim3(NOUTD / 128, BATCH / 128), blk>>>(
        o_alpha, Psi, o_yhat, NOUTD, NCODE, o_ybg, nullptr, nullptr, 0);
}

// round 4
// speedup vs baseline: 2.4916x; 2.4916x over previous
#include <cuda_runtime.h>
#include <cuda_bf16.h>
#include <math.h>
#include <stdint.h>

typedef __nv_bfloat16 bf16;

#define BATCH 8192
#define PDIM  512
#define H1DIM 1024
#define H2DIM 512
#define NOUTD 1024
#define MMDIM 512
#define NCODE 2048
#define KSTEPS 16

// ---------------- device scratch (no allocations allowed) -------------------
__device__ float g_v [(size_t)BATCH * NCODE];   // FISTA v (fp32, epilogue aux)
__device__ float g_a0[(size_t)BATCH * NCODE];   // alpha (fp32, epilogue aux2)

__device__ bf16 g_xsh[(size_t)BATCH*PDIM],  g_xsl[(size_t)BATCH*PDIM];
__device__ bf16 g_h1h[(size_t)BATCH*H1DIM], g_h1l[(size_t)BATCH*H1DIM];
__device__ bf16 g_h2h[(size_t)BATCH*H2DIM], g_h2l[(size_t)BATCH*H2DIM];
__device__ bf16 g_ybh[(size_t)BATCH*NOUTD], g_ybl[(size_t)BATCH*NOUTD];
__device__ bf16 g_vh [(size_t)BATCH*NCODE], g_vl [(size_t)BATCH*NCODE];
__device__ bf16 g_rh [(size_t)BATCH*MMDIM], g_rl [(size_t)BATCH*MMDIM];
__device__ bf16 g_aph[(size_t)BATCH*NCODE], g_apl[(size_t)BATCH*NCODE];

__device__ bf16 g_w1h[(size_t)H1DIM*PDIM],  g_w1l[(size_t)H1DIM*PDIM];   // W1^T
__device__ bf16 g_w2h[(size_t)H2DIM*H1DIM], g_w2l[(size_t)H2DIM*H1DIM];  // W2^T
__device__ bf16 g_w3h[(size_t)NOUTD*H2DIM], g_w3l[(size_t)NOUTD*H2DIM];  // W3^T
__device__ bf16 g_mh [(size_t)MMDIM*NOUTD], g_ml [(size_t)MMDIM*NOUTD];  // M (as stored)
__device__ bf16 g_aah[(size_t)MMDIM*NCODE], g_aal[(size_t)MMDIM*NCODE];  // A (as stored)
__device__ bf16 g_ath[(size_t)NCODE*MMDIM], g_atl[(size_t)NCODE*MMDIM];  // A^T
__device__ bf16 g_psh[(size_t)NOUTD*NCODE], g_psl[(size_t)NOUTD*NCODE];  // Psi (as stored)

// ---------------- PTX helpers (all legal on base compute_103 target) --------
__device__ __forceinline__ uint32_t smem_u32(const void* p) {
    uint32_t a;
    asm("{ .reg .u64 t; cvta.to.shared.u64 t, %1; cvt.u32.u64 %0, t; }" : "=r"(a) : "l"(p));
    return a;
}
__device__ __forceinline__ void cp16(uint32_t d, const void* s) {
    asm volatile("cp.async.cg.shared.global [%0], [%1], 16;" :: "r"(d), "l"(s) : "memory");
}
#define CP_COMMIT() asm volatile("cp.async.commit_group;" ::: "memory")
#define CP_WAIT0()  asm volatile("cp.async.wait_group 0;" ::: "memory")

#define LDSM4(r0, r1, r2, r3, a) \
    asm volatile("ldmatrix.sync.aligned.m8n8.x4.shared.b16 {%0,%1,%2,%3}, [%4];" \
                 : "=r"(r0), "=r"(r1), "=r"(r2), "=r"(r3) : "r"(a))

#define MMA16816(c, a, b) \
    asm volatile("mma.sync.aligned.m16n8k16.row.col.f32.bf16.bf16.f32 " \
                 "{%0,%1,%2,%3}, {%4,%5,%6,%7}, {%8,%9}, {%0,%1,%2,%3};" \
                 : "+f"((c)[0]), "+f"((c)[1]), "+f"((c)[2]), "+f"((c)[3]) \
                 : "r"((a)[0]), "r"((a)[1]), "r"((a)[2]), "r"((a)[3]), \
                   "r"((b)[0]), "r"((b)[1]))

// ---------------- GEMM constants ---------------------------------------------
// SMEM tile: 128 rows x 64 bf16, padded row stride 72 bf16 = 144 B (9x16B:
// conflict-free ldmatrix phases since row*9 mod 8 distinct for 8 rows).
#define ROW_B   144
#define TILE_B  (128 * ROW_B)            // 18432 B per operand tile
#define STAGE_B (4 * TILE_B)             // Ah,Al,Bh,Bl = 73728 B
#define SMEM_BYTES (2 * STAGE_B)         // 147456 B

enum { EPI_GELU = 0, EPI_YBG, EPI_ZSUB, EPI_RSUB, EPI_FISTA, EPI_ADD };

__device__ __forceinline__ float gelu_exact(float x) {
    return 0.5f * x * (1.0f + erff(x * 0.70710678118654752440f));
}
__device__ __forceinline__ void split2(bf16* H, bf16* L, size_t idx, float o0, float o1) {
    bf16 h0 = __float2bfloat16(o0), h1 = __float2bfloat16(o1);
    bf16 l0 = __float2bfloat16(o0 - __bfloat162float(h0));
    bf16 l1 = __float2bfloat16(o1 - __bfloat162float(h1));
    *(__nv_bfloat162*)(H + idx) = __halves2bfloat162(h0, h1);
    *(__nv_bfloat162*)(L + idx) = __halves2bfloat162(l0, l1);
}

// ---------------------------------------------------------------------------
// Warp-MMA GEMM: D[128,128 tiles] = (Ah+Al)[M,K] * ((Bh+Bl)[N,K])^T, fp32 acc,
// 3 bf16 products (AhBh + AlBh + AhBl), fused epilogue.
// ---------------------------------------------------------------------------
template <int EPI>
__global__ void __launch_bounds__(256, 1)
wgemm(const bf16* __restrict__ Agh, const bf16* __restrict__ Agl,
      const bf16* __restrict__ Bgh, const bf16* __restrict__ Bgl,
      int Ndim, int Kdim,
      float* __restrict__ C0, bf16* __restrict__ Ch, bf16* __restrict__ Cl,
      const float* __restrict__ aux, const float* __restrict__ aux2,
      float* __restrict__ vout, bf16* __restrict__ vho, bf16* __restrict__ vlo,
      const float* __restrict__ leta, const float* __restrict__ ltau,
      int kidx, float beta)
{
    extern __shared__ char dyn[];
    const uint32_t sbase = smem_u32(dyn);

    const int tid = threadIdx.x;
    const int wid = tid >> 5;
    const int lid = tid & 31;
    const int m0  = blockIdx.y * 128;
    const int n0  = blockIdx.x * 128;
    const int m_w = (wid >> 2) * 64;     // warp m offset (2 rows of warps)
    const int n_w = (wid & 3) * 32;      // warp n offset (4 cols of warps)

    // ---- loader plan: 16 cp.async x 16B per thread per stage -----------------
    const bf16* gp[16];
    uint32_t so[16];
    {
        const bf16* srcs[4] = { Agh, Agl, Bgh, Bgl };
#pragma unroll
        for (int it = 0; it < 16; it++) {
            const int op  = it >> 2;                    // 0:Ah 1:Al 2:Bh 3:Bl
            const int row = (it & 3) * 32 + (tid >> 3);
            const int seg = tid & 7;                    // 8 bf16 per 16B seg
            const int rb  = (op < 2) ? m0 : n0;
            gp[it] = srcs[op] + (size_t)(rb + row) * Kdim + seg * 8;
            so[it] = (uint32_t)(op * TILE_B + row * ROW_B + seg * 16);
        }
    }

    // ---- ldmatrix per-lane offsets -------------------------------------------
    const int aRow = (lid & 7) + ((lid >> 3) & 1) * 8;
    const int aK   = ((lid >> 4) & 1) * 8;
    const int bRow = (lid & 7) + ((lid >> 4) & 1) * 8;
    const int bK   = ((lid >> 3) & 1) * 8;
    const uint32_t aOff = (uint32_t)((m_w + aRow) * ROW_B + aK * 2);
    const uint32_t bOff = (uint32_t)((n_w + bRow) * ROW_B + bK * 2);

    float acc[4][4][4];
#pragma unroll
    for (int i = 0; i < 4; i++)
#pragma unroll
        for (int j = 0; j < 4; j++)
#pragma unroll
            for (int c = 0; c < 4; c++) acc[i][j][c] = 0.0f;

    const int S = Kdim >> 6;

    // prologue: stage 0 -> buf 0
#pragma unroll
    for (int it = 0; it < 16; it++) cp16(sbase + so[it], gp[it]);
    CP_COMMIT();

    for (int s = 0; s < S; s++) {
        CP_WAIT0();
        __syncthreads();
        if (s + 1 < S) {
            const uint32_t db = sbase + (uint32_t)(((s + 1) & 1) * STAGE_B);
            const int k0 = (s + 1) * 64;
#pragma unroll
            for (int it = 0; it < 16; it++) cp16(db + so[it], gp[it] + k0);
            CP_COMMIT();
        }
        const uint32_t st = sbase + (uint32_t)((s & 1) * STAGE_B);

#pragma unroll
        for (int kk = 0; kk < 4; kk++) {
            uint32_t ah[4][4], al[4][4], bh[4][2], bl[4][2];
#pragma unroll
            for (int i = 0; i < 4; i++) {
                LDSM4(ah[i][0], ah[i][1], ah[i][2], ah[i][3],
                      st + aOff + i * (16 * ROW_B) + kk * 32);
                LDSM4(al[i][0], al[i][1], al[i][2], al[i][3],
                      st + TILE_B + aOff + i * (16 * ROW_B) + kk * 32);
            }
#pragma unroll
            for (int j = 0; j < 2; j++) {
                uint32_t r0, r1, r2, r3;
                LDSM4(r0, r1, r2, r3,
                      st + 2 * TILE_B + bOff + j * (16 * ROW_B) + kk * 32);
                bh[2 * j][0] = r0; bh[2 * j][1] = r1;
                bh[2 * j + 1][0] = r2; bh[2 * j + 1][1] = r3;
                LDSM4(r0, r1, r2, r3,
                      st + 3 * TILE_B + bOff + j * (16 * ROW_B) + kk * 32);
                bl[2 * j][0] = r0; bl[2 * j][1] = r1;
                bl[2 * j + 1][0] = r2; bl[2 * j + 1][1] = r3;
            }
#pragma unroll
            for (int i = 0; i < 4; i++)
#pragma unroll
                for (int j = 0; j < 4; j++) {
                    MMA16816(acc[i][j], ah[i], bh[j]);
                    MMA16816(acc[i][j], al[i], bh[j]);
                    MMA16816(acc[i][j], ah[i], bl[j]);
                }
        }
    }

    // ---- fused epilogue -------------------------------------------------------
    float eta = 0.0f, thr = 0.0f;
    if (EPI == EPI_FISTA) {
        eta = expf(leta[kidx]);  eta = fminf(fmaxf(eta, 1e-8f), 10.0f);
        float tau = expf(ltau[kidx]); tau = fminf(fmaxf(tau, 1e-8f), 10.0f);
        thr = eta * tau;
    }

#pragma unroll
    for (int i = 0; i < 4; i++) {
#pragma unroll
        for (int j = 0; j < 4; j++) {
#pragma unroll
            for (int half = 0; half < 2; half++) {
                const int row = m0 + m_w + i * 16 + (lid >> 2) + half * 8;
                const int col = n0 + n_w + j * 8 + (lid & 3) * 2;
                const size_t idx = (size_t)row * Ndim + col;
                float o0 = acc[i][j][half * 2];
                float o1 = acc[i][j][half * 2 + 1];

                if (EPI == EPI_GELU) {
                    float2 bv = *(const float2*)&aux[col];
                    o0 = gelu_exact(o0 + bv.x);
                    o1 = gelu_exact(o1 + bv.y);
                    split2(Ch, Cl, idx, o0, o1);
                } else if (EPI == EPI_YBG) {
                    float2 bv = *(const float2*)&aux[col];
                    o0 += bv.x; o1 += bv.y;
                    *(float2*)&C0[idx] = make_float2(o0, o1);
                    split2(Ch, Cl, idx, o0, o1);
                } else if (EPI == EPI_ZSUB) {               // z = b - acc
                    float2 av = *(const float2*)&aux[idx];
                    *(float2*)&C0[idx] = make_float2(av.x - o0, av.y - o1);
                } else if (EPI == EPI_RSUB) {               // r = acc - z (bf16 out)
                    float2 av = *(const float2*)&aux[idx];
                    o0 -= av.x; o1 -= av.y;
                    split2(Ch, Cl, idx, o0, o1);
                } else if (EPI == EPI_FISTA) {
                    float2 vv = *(const float2*)&aux[idx];   // v
                    float u0 = vv.x - eta * o0, u1 = vv.y - eta * o1;
                    float a0n = copysignf(fmaxf(fabsf(u0) - thr, 0.0f), u0);
                    float a1n = copysignf(fmaxf(fabsf(u1) - thr, 0.0f), u1);
                    if (vout) {
                        float2 ao = *(const float2*)&aux2[idx];  // alpha_old
                        float v0 = a0n + beta * (a0n - ao.x);
                        float v1 = a1n + beta * (a1n - ao.y);
                        *(float2*)&C0[idx]   = make_float2(a0n, a1n);
                        *(float2*)&vout[idx] = make_float2(v0, v1);
                        split2(vho, vlo, idx, v0, v1);
                    } else {
                        *(float2*)&C0[idx] = make_float2(a0n, a1n);
                        split2(Ch, Cl, idx, a0n, a1n);
                    }
                } else {                                    // EPI_ADD
                    float2 yv = *(const float2*)&aux[idx];
                    *(float2*)&C0[idx] = make_float2(o0 + yv.x, o1 + yv.y);
                }
            }
        }
    }
}

// ---------------- prep kernels ------------------------------------------------
__global__ void split_kernel(const float4* __restrict__ s, bf16* __restrict__ h,
                             bf16* __restrict__ l, int n4)
{
    int i = blockIdx.x * blockDim.x + threadIdx.x;
    if (i < n4) {
        float4 v = s[i];
        size_t idx = (size_t)i * 4;
        bf16 h0 = __float2bfloat16(v.x), h1 = __float2bfloat16(v.y);
        bf16 h2 = __float2bfloat16(v.z), h3 = __float2bfloat16(v.w);
        *(__nv_bfloat162*)(h + idx)     = __halves2bfloat162(h0, h1);
        *(__nv_bfloat162*)(h + idx + 2) = __halves2bfloat162(h2, h3);
        bf16 l0 = __float2bfloat16(v.x - __bfloat162float(h0));
        bf16 l1 = __float2bfloat16(v.y - __bfloat162float(h1));
        bf16 l2 = __float2bfloat16(v.z - __bfloat162float(h2));
        bf16 l3 = __float2bfloat16(v.w - __bfloat162float(h3));
        *(__nv_bfloat162*)(l + idx)     = __halves2bfloat162(l0, l1);
        *(__nv_bfloat162*)(l + idx + 2) = __halves2bfloat162(l2, l3);
    }
}

// transpose + split: src [R,C] fp32 -> dst [C,R] bf16 hi/lo
__global__ void tsplit_kernel(const float* __restrict__ s, bf16* __restrict__ oh,
                              bf16* __restrict__ ol, int R, int C)
{
    __shared__ float t[32][33];
    const int bx = blockIdx.x * 32;   // C offset
    const int by = blockIdx.y * 32;   // R offset
    const int x = threadIdx.x, y = threadIdx.y;
#pragma unroll
    for (int i = 0; i < 4; i++)
        t[y + i * 8][x] = s[(size_t)(by + y + i * 8) * C + bx + x];
    __syncthreads();
#pragma unroll
    for (int i = 0; i < 4; i++) {
        float v = t[x][y + i * 8];
        size_t idx = (size_t)(bx + y + i * 8) * R + by + x;
        bf16 h = __float2bfloat16(v);
        oh[idx] = h;
        ol[idx] = __float2bfloat16(v - __bfloat162float(h));
    }
}

__global__ void fill0_kernel(float4* __restrict__ p, int n4)
{
    int i = blockIdx.x * blockDim.x + threadIdx.x;
    if (i < n4) p[i] = make_float4(0.f, 0.f, 0.f, 0.f);
}

// ---------------------------------------------------------------------------
extern "C" void kernel_launch(void* const* d_in, const int* in_sizes, int n_in,
                              void* d_out, int out_size)
{
    const float* x    = (const float*)d_in[0];
    const float* bvec = (const float*)d_in[1];
    const float* W1   = (const float*)d_in[2];
    const float* b1   = (const float*)d_in[3];
    const float* W2   = (const float*)d_in[4];
    const float* b2   = (const float*)d_in[5];
    const float* W3   = (const float*)d_in[6];
    const float* b3   = (const float*)d_in[7];
    const float* A    = (const float*)d_in[8];
    const float* leta = (const float*)d_in[9];
    const float* ltau = (const float*)d_in[10];
    const float* Psi  = (const float*)d_in[11];
    const float* Mmat = (const float*)d_in[12];

    float* out     = (float*)d_out;
    float* o_ybg   = out;
    float* o_z     = o_ybg   + (size_t)BATCH * NOUTD;
    float* o_alpha = o_z     + (size_t)BATCH * MMDIM;
    float* o_yhat  = o_alpha + (size_t)BATCH * NCODE;

#define SYM(p, s) void* p##_; cudaGetSymbolAddress(&p##_, s); auto* p = (decltype(&s[0]))p##_
    SYM(vbuf, g_v);  SYM(abuf, g_a0);
    SYM(xsh, g_xsh); SYM(xsl, g_xsl);
    SYM(h1h, g_h1h); SYM(h1l, g_h1l);
    SYM(h2h, g_h2h); SYM(h2l, g_h2l);
    SYM(ybh, g_ybh); SYM(ybl, g_ybl);
    SYM(vh, g_vh);   SYM(vl, g_vl);
    SYM(rh, g_rh);   SYM(rl, g_rl);
    SYM(aph, g_aph); SYM(apl, g_apl);
    SYM(w1h, g_w1h); SYM(w1l, g_w1l);
    SYM(w2h, g_w2h); SYM(w2l, g_w2l);
    SYM(w3h, g_w3h); SYM(w3l, g_w3l);
    SYM(mh, g_mh);   SYM(ml, g_ml);
    SYM(aah, g_aah); SYM(aal, g_aal);
    SYM(ath, g_ath); SYM(atl, g_atl);
    SYM(psh, g_psh); SYM(psl, g_psl);
#undef SYM

    cudaFuncSetAttribute((void*)wgemm<EPI_GELU>,  cudaFuncAttributeMaxDynamicSharedMemorySize, SMEM_BYTES);
    cudaFuncSetAttribute((void*)wgemm<EPI_YBG>,   cudaFuncAttributeMaxDynamicSharedMemorySize, SMEM_BYTES);
    cudaFuncSetAttribute((void*)wgemm<EPI_ZSUB>,  cudaFuncAttributeMaxDynamicSharedMemorySize, SMEM_BYTES);
    cudaFuncSetAttribute((void*)wgemm<EPI_RSUB>,  cudaFuncAttributeMaxDynamicSharedMemorySize, SMEM_BYTES);
    cudaFuncSetAttribute((void*)wgemm<EPI_FISTA>, cudaFuncAttributeMaxDynamicSharedMemorySize, SMEM_BYTES);
    cudaFuncSetAttribute((void*)wgemm<EPI_ADD>,   cudaFuncAttributeMaxDynamicSharedMemorySize, SMEM_BYTES);

    // host-side FISTA momentum (data-independent)
    float betas[KSTEPS + 1];
    {
        float t = 1.0f; betas[0] = 0.0f;
        for (int k = 1; k <= KSTEPS; k++) {
            float tn = 0.5f * (1.0f + sqrtf(1.0f + 4.0f * t * t));
            betas[k] = (t - 1.0f) / tn;
            t = tn;
        }
    }

    // ---- prep: splits / transposes / zero fills -----------------------------
    auto splits = [&](const float* s, bf16* h, bf16* l, size_t n) {
        int n4 = (int)(n / 4);
        split_kernel<<<(n4 + 255) / 256, 256>>>((const float4*)s, h, l, n4);
    };
    splits(x,    xsh, xsl, (size_t)BATCH * PDIM);
    splits(A,    aah, aal, (size_t)MMDIM * NCODE);
    splits(Mmat, mh,  ml,  (size_t)MMDIM * NOUTD);
    splits(Psi,  psh, psl, (size_t)NOUTD * NCODE);
    tsplit_kernel<<<dim3(H1DIM / 32, PDIM / 32),  dim3(32, 8)>>>(W1, w1h, w1l, PDIM,  H1DIM);
    tsplit_kernel<<<dim3(H2DIM / 32, H1DIM / 32), dim3(32, 8)>>>(W2, w2h, w2l, H1DIM, H2DIM);
    tsplit_kernel<<<dim3(NOUTD / 32, H2DIM / 32), dim3(32, 8)>>>(W3, w3h, w3l, H2DIM, NOUTD);
    tsplit_kernel<<<dim3(NCODE / 32, MMDIM / 32), dim3(32, 8)>>>(A,  ath, atl, MMDIM, NCODE);

    const int nA = BATCH * NCODE;
    fill0_kernel<<<(nA / 4 + 255) / 256, 256>>>((float4*)vbuf, nA / 4);
    fill0_kernel<<<(nA / 4 + 255) / 256, 256>>>((float4*)abuf, nA / 4);
    fill0_kernel<<<(nA / 8 + 255) / 256, 256>>>((float4*)vh, nA / 8);
    fill0_kernel<<<(nA / 8 + 255) / 256, 256>>>((float4*)vl, nA / 8);

    const dim3 blk(256);
#define GRID(N) dim3((N) / 128, BATCH / 128)

    // ---- background MLP -----------------------------------------------------
    wgemm<EPI_GELU><<<GRID(H1DIM), blk, SMEM_BYTES>>>(
        xsh, xsl, w1h, w1l, H1DIM, PDIM, nullptr, h1h, h1l,
        b1, nullptr, nullptr, nullptr, nullptr, nullptr, nullptr, 0, 0.f);
    wgemm<EPI_GELU><<<GRID(H2DIM), blk, SMEM_BYTES>>>(
        h1h, h1l, w2h, w2l, H2DIM, H1DIM, nullptr, h2h, h2l,
        b2, nullptr, nullptr, nullptr, nullptr, nullptr, nullptr, 0, 0.f);
    wgemm<EPI_YBG><<<GRID(NOUTD), blk, SMEM_BYTES>>>(
        h2h, h2l, w3h, w3l, NOUTD, H2DIM, o_ybg, ybh, ybl,
        b3, nullptr, nullptr, nullptr, nullptr, nullptr, nullptr, 0, 0.f);

    // ---- z = b - y_bg @ M^T --------------------------------------------------
    wgemm<EPI_ZSUB><<<GRID(MMDIM), blk, SMEM_BYTES>>>(
        ybh, ybl, mh, ml, MMDIM, NOUTD, o_z, nullptr, nullptr,
        bvec, nullptr, nullptr, nullptr, nullptr, nullptr, nullptr, 0, 0.f);

    // ---- FISTA loop (vcomb fused into EPI_FISTA epilogue) --------------------
    for (int k = 0; k < KSTEPS; k++) {
        // r = v @ A^T - z  (bf16 hi/lo out)
        wgemm<EPI_RSUB><<<GRID(MMDIM), blk, SMEM_BYTES>>>(
            vh, vl, aah, aal, MMDIM, NCODE, nullptr, rh, rl,
            o_z, nullptr, nullptr, nullptr, nullptr, nullptr, nullptr, 0, 0.f);
        // alpha_new = soft(v - eta*(r @ A), eta*tau);  v_next fused
        if (k < KSTEPS - 1) {
            wgemm<EPI_FISTA><<<GRID(NCODE), blk, SMEM_BYTES>>>(
                rh, rl, ath, atl, NCODE, MMDIM, abuf, nullptr, nullptr,
                vbuf, abuf, vbuf, vh, vl, leta, ltau, k, betas[k + 1]);
        } else {
            wgemm<EPI_FISTA><<<GRID(NCODE), blk, SMEM_BYTES>>>(
                rh, rl, ath, atl, NCODE, MMDIM, o_alpha, aph, apl,
                vbuf, abuf, nullptr, nullptr, nullptr, leta, ltau, k, 0.f);
        }
    }

    // ---- y_hat = y_bg + alpha @ Psi^T ----------------------------------------
    wgemm<EPI_ADD><<<GRID(NOUTD), blk, SMEM_BYTES>>>(
        aph, apl, psh, psl, NOUTD, NCODE, o_yhat, nullptr, nullptr,
        o_ybg, nullptr, nullptr, nullptr, nullptr, nullptr, nullptr, 0, 0.f);
}

// round 5
// speedup vs baseline: 3.3711x; 1.3529x over previous
#include <cuda_runtime.h>
#include <cuda_fp16.h>
#include <math.h>
#include <stdint.h>

typedef __half fp16;

#define BATCH 8192
#define PDIM  512
#define H1DIM 1024
#define H2DIM 512
#define NOUTD 1024
#define MMDIM 512
#define NCODE 2048
#define KSTEPS 16

// ---------------- device scratch (no allocations allowed) -------------------
__device__ float g_v [(size_t)BATCH * NCODE];   // FISTA v (fp32, epilogue aux)
__device__ float g_a0[(size_t)BATCH * NCODE];   // alpha (fp32, epilogue aux2)

// activations: fp16 hi/lo
__device__ fp16 g_xsh[(size_t)BATCH*PDIM],  g_xsl[(size_t)BATCH*PDIM];
__device__ fp16 g_h1h[(size_t)BATCH*H1DIM], g_h1l[(size_t)BATCH*H1DIM];
__device__ fp16 g_h2h[(size_t)BATCH*H2DIM], g_h2l[(size_t)BATCH*H2DIM];
__device__ fp16 g_ybh[(size_t)BATCH*NOUTD], g_ybl[(size_t)BATCH*NOUTD];
__device__ fp16 g_vh [(size_t)BATCH*NCODE], g_vl [(size_t)BATCH*NCODE];
__device__ fp16 g_rh [(size_t)BATCH*MMDIM], g_rl [(size_t)BATCH*MMDIM];
__device__ fp16 g_aph[(size_t)BATCH*NCODE], g_apl[(size_t)BATCH*NCODE];

// weights / operators: single fp16 (rounded once)
__device__ fp16 g_w1[(size_t)H1DIM*PDIM];    // W1^T
__device__ fp16 g_w2[(size_t)H2DIM*H1DIM];   // W2^T
__device__ fp16 g_w3[(size_t)NOUTD*H2DIM];   // W3^T
__device__ fp16 g_m [(size_t)MMDIM*NOUTD];   // M  (as stored)
__device__ fp16 g_aa[(size_t)MMDIM*NCODE];   // A  (as stored)
__device__ fp16 g_at[(size_t)NCODE*MMDIM];   // A^T
__device__ fp16 g_ps[(size_t)NOUTD*NCODE];   // Psi (as stored)

// ---------------- PTX helpers (legal on base compute_103 target) ------------
__device__ __forceinline__ uint32_t smem_u32(const void* p) {
    uint32_t a;
    asm("{ .reg .u64 t; cvta.to.shared.u64 t, %1; cvt.u32.u64 %0, t; }" : "=r"(a) : "l"(p));
    return a;
}
__device__ __forceinline__ void cp16(uint32_t d, const void* s) {
    asm volatile("cp.async.cg.shared.global [%0], [%1], 16;" :: "r"(d), "l"(s) : "memory");
}
#define CP_COMMIT() asm volatile("cp.async.commit_group;" ::: "memory")
#define CP_WAIT0()  asm volatile("cp.async.wait_group 0;" ::: "memory")
#define CP_WAIT1()  asm volatile("cp.async.wait_group 1;" ::: "memory")

#define LDSM4(r0, r1, r2, r3, a) \
    asm volatile("ldmatrix.sync.aligned.m8n8.x4.shared.b16 {%0,%1,%2,%3}, [%4];" \
                 : "=r"(r0), "=r"(r1), "=r"(r2), "=r"(r3) : "r"(a))

#define MMA16816(c, a, b) \
    asm volatile("mma.sync.aligned.m16n8k16.row.col.f32.f16.f16.f32 " \
                 "{%0,%1,%2,%3}, {%4,%5,%6,%7}, {%8,%9}, {%0,%1,%2,%3};" \
                 : "+f"((c)[0]), "+f"((c)[1]), "+f"((c)[2]), "+f"((c)[3]) \
                 : "r"((a)[0]), "r"((a)[1]), "r"((a)[2]), "r"((a)[3]), \
                   "r"((b)[0]), "r"((b)[1]))

// ---------------- GEMM constants ---------------------------------------------
// SMEM tile: 128 rows x 64 fp16, padded row stride 72 fp16 = 144 B
// (9x16B -> conflict-free ldmatrix phases).
#define ROW_B   144
#define TILE_B  (128 * ROW_B)            // 18432 B per operand tile
#define STAGE_B (3 * TILE_B)             // Ah, Al, B = 55296 B
#define SMEM_BYTES (3 * STAGE_B)         // 3 stages = 165888 B

enum { EPI_GELU = 0, EPI_YBG, EPI_ZSUB, EPI_RSUB, EPI_FISTA, EPI_ADD };

__device__ __forceinline__ float gelu_exact(float x) {
    return 0.5f * x * (1.0f + erff(x * 0.70710678118654752440f));
}
__device__ __forceinline__ void split2h(fp16* H, fp16* L, size_t idx, float o0, float o1) {
    fp16 h0 = __float2half_rn(o0), h1 = __float2half_rn(o1);
    fp16 l0 = __float2half_rn(o0 - __half2float(h0));
    fp16 l1 = __float2half_rn(o1 - __half2float(h1));
    *(__half2*)(H + idx) = __halves2half2(h0, h1);
    *(__half2*)(L + idx) = __halves2half2(l0, l1);
}

// ---------------------------------------------------------------------------
// Warp-MMA GEMM: D[128x128 tile] = (Ah+Al)[M,K] * (B[N,K])^T, fp32 acc,
// 2 fp16 products (AhB + AlB), 3-stage cp.async pipeline, fused epilogue.
// ---------------------------------------------------------------------------
template <int EPI>
__global__ void __launch_bounds__(256, 1)
wgemm(const fp16* __restrict__ Agh, const fp16* __restrict__ Agl,
      const fp16* __restrict__ Bg,
      int Ndim, int Kdim,
      float* __restrict__ C0, fp16* __restrict__ Ch, fp16* __restrict__ Cl,
      const float* __restrict__ aux, const float* __restrict__ aux2,
      float* __restrict__ vout, fp16* __restrict__ vho, fp16* __restrict__ vlo,
      const float* __restrict__ leta, const float* __restrict__ ltau,
      int kidx, float beta)
{
    extern __shared__ char dyn[];
    const uint32_t sbase = smem_u32(dyn);

    const int tid = threadIdx.x;
    const int wid = tid >> 5;
    const int lid = tid & 31;
    const int m0  = blockIdx.y * 128;
    const int n0  = blockIdx.x * 128;
    const int m_w = (wid >> 2) * 64;     // warp m offset
    const int n_w = (wid & 3) * 32;      // warp n offset

    // ---- loader plan: 12 cp.async x 16B per thread per stage -----------------
    const fp16* gp[12];
    uint32_t so[12];
    {
        const fp16* srcs[3] = { Agh, Agl, Bg };
#pragma unroll
        for (int it = 0; it < 12; it++) {
            const int op  = it >> 2;                    // 0:Ah 1:Al 2:B
            const int row = (it & 3) * 32 + (tid >> 3);
            const int seg = tid & 7;                    // 8 fp16 per 16B
            const int rb  = (op < 2) ? m0 : n0;
            gp[it] = srcs[op] + (size_t)(rb + row) * Kdim + seg * 8;
            so[it] = (uint32_t)(op * TILE_B + row * ROW_B + seg * 16);
        }
    }

    // ---- ldmatrix per-lane offsets -------------------------------------------
    const int aRow = (lid & 7) + ((lid >> 3) & 1) * 8;
    const int aK   = ((lid >> 4) & 1) * 8;
    const int bRow = (lid & 7) + ((lid >> 4) & 1) * 8;
    const int bK   = ((lid >> 3) & 1) * 8;
    const uint32_t aOff = (uint32_t)((m_w + aRow) * ROW_B + aK * 2);
    const uint32_t bOff = (uint32_t)((n_w + bRow) * ROW_B + bK * 2);

    float acc[4][4][4];
#pragma unroll
    for (int i = 0; i < 4; i++)
#pragma unroll
        for (int j = 0; j < 4; j++)
#pragma unroll
            for (int c = 0; c < 4; c++) acc[i][j][c] = 0.0f;

    const int S = Kdim >> 6;   // K-chunks of 64

    // prologue: stages 0,1 -> bufs 0,1
#pragma unroll
    for (int it = 0; it < 12; it++) cp16(sbase + so[it], gp[it]);
    CP_COMMIT();
    if (S > 1) {
#pragma unroll
        for (int it = 0; it < 12; it++) cp16(sbase + STAGE_B + so[it], gp[it] + 64);
        CP_COMMIT();
    }

    int cb = 0, pb = 2;   // compute buf (s%3), prefetch buf ((s+2)%3)
    for (int s = 0; s < S; s++) {
        if (s + 2 < S) { CP_WAIT1(); } else { CP_WAIT0(); }
        __syncthreads();
        if (s + 2 < S) {
            const uint32_t db = sbase + (uint32_t)(pb * STAGE_B);
            const int k0 = (s + 2) * 64;
#pragma unroll
            for (int it = 0; it < 12; it++) cp16(db + so[it], gp[it] + k0);
            CP_COMMIT();
        }
        const uint32_t st = sbase + (uint32_t)(cb * STAGE_B);

#pragma unroll
        for (int kk = 0; kk < 4; kk++) {
            uint32_t ah[4][4], al[4][4], bh[4][2];
#pragma unroll
            for (int i = 0; i < 4; i++) {
                LDSM4(ah[i][0], ah[i][1], ah[i][2], ah[i][3],
                      st + aOff + i * (16 * ROW_B) + kk * 32);
                LDSM4(al[i][0], al[i][1], al[i][2], al[i][3],
                      st + TILE_B + aOff + i * (16 * ROW_B) + kk * 32);
            }
#pragma unroll
            for (int j = 0; j < 2; j++) {
                uint32_t r0, r1, r2, r3;
                LDSM4(r0, r1, r2, r3,
                      st + 2 * TILE_B + bOff + j * (16 * ROW_B) + kk * 32);
                bh[2 * j][0] = r0; bh[2 * j][1] = r1;
                bh[2 * j + 1][0] = r2; bh[2 * j + 1][1] = r3;
            }
#pragma unroll
            for (int i = 0; i < 4; i++)
#pragma unroll
                for (int j = 0; j < 4; j++) {
                    MMA16816(acc[i][j], ah[i], bh[j]);
                    MMA16816(acc[i][j], al[i], bh[j]);
                }
        }
        cb = (cb == 2) ? 0 : cb + 1;
        pb = (pb == 2) ? 0 : pb + 1;
    }

    // ---- fused epilogue -------------------------------------------------------
    float eta = 0.0f, thr = 0.0f;
    if (EPI == EPI_FISTA) {
        eta = expf(leta[kidx]);  eta = fminf(fmaxf(eta, 1e-8f), 10.0f);
        float tau = expf(ltau[kidx]); tau = fminf(fmaxf(tau, 1e-8f), 10.0f);
        thr = eta * tau;
    }

#pragma unroll
    for (int i = 0; i < 4; i++) {
#pragma unroll
        for (int j = 0; j < 4; j++) {
#pragma unroll
            for (int half = 0; half < 2; half++) {
                const int row = m0 + m_w + i * 16 + (lid >> 2) + half * 8;
                const int col = n0 + n_w + j * 8 + (lid & 3) * 2;
                const size_t idx = (size_t)row * Ndim + col;
                float o0 = acc[i][j][half * 2];
                float o1 = acc[i][j][half * 2 + 1];

                if (EPI == EPI_GELU) {
                    float2 bv = *(const float2*)&aux[col];
                    o0 = gelu_exact(o0 + bv.x);
                    o1 = gelu_exact(o1 + bv.y);
                    split2h(Ch, Cl, idx, o0, o1);
                } else if (EPI == EPI_YBG) {
                    float2 bv = *(const float2*)&aux[col];
                    o0 += bv.x; o1 += bv.y;
                    *(float2*)&C0[idx] = make_float2(o0, o1);
                    split2h(Ch, Cl, idx, o0, o1);
                } else if (EPI == EPI_ZSUB) {               // z = b - acc
                    float2 av = *(const float2*)&aux[idx];
                    *(float2*)&C0[idx] = make_float2(av.x - o0, av.y - o1);
                } else if (EPI == EPI_RSUB) {               // r = acc - z (fp16 out)
                    float2 av = *(const float2*)&aux[idx];
                    o0 -= av.x; o1 -= av.y;
                    split2h(Ch, Cl, idx, o0, o1);
                } else if (EPI == EPI_FISTA) {
                    float2 vv = *(const float2*)&aux[idx];   // v
                    float u0 = vv.x - eta * o0, u1 = vv.y - eta * o1;
                    float a0n = copysignf(fmaxf(fabsf(u0) - thr, 0.0f), u0);
                    float a1n = copysignf(fmaxf(fabsf(u1) - thr, 0.0f), u1);
                    if (vout) {
                        float2 ao = *(const float2*)&aux2[idx];  // alpha_old
                        float v0 = a0n + beta * (a0n - ao.x);
                        float v1 = a1n + beta * (a1n - ao.y);
                        *(float2*)&C0[idx]   = make_float2(a0n, a1n);
                        *(float2*)&vout[idx] = make_float2(v0, v1);
                        split2h(vho, vlo, idx, v0, v1);
                    } else {
                        *(float2*)&C0[idx] = make_float2(a0n, a1n);
                        split2h(Ch, Cl, idx, a0n, a1n);
                    }
                } else {                                    // EPI_ADD
                    float2 yv = *(const float2*)&aux[idx];
                    *(float2*)&C0[idx] = make_float2(o0 + yv.x, o1 + yv.y);
                }
            }
        }
    }
}

// ---------------- prep kernels ------------------------------------------------
__global__ void split_kernel(const float4* __restrict__ s, fp16* __restrict__ h,
                             fp16* __restrict__ l, int n4)
{
    int i = blockIdx.x * blockDim.x + threadIdx.x;
    if (i < n4) {
        float4 v = s[i];
        size_t idx = (size_t)i * 4;
        fp16 h0 = __float2half_rn(v.x), h1 = __float2half_rn(v.y);
        fp16 h2 = __float2half_rn(v.z), h3 = __float2half_rn(v.w);
        *(__half2*)(h + idx)     = __halves2half2(h0, h1);
        *(__half2*)(h + idx + 2) = __halves2half2(h2, h3);
        fp16 l0 = __float2half_rn(v.x - __half2float(h0));
        fp16 l1 = __float2half_rn(v.y - __half2float(h1));
        fp16 l2 = __float2half_rn(v.z - __half2float(h2));
        fp16 l3 = __float2half_rn(v.w - __half2float(h3));
        *(__half2*)(l + idx)     = __halves2half2(l0, l1);
        *(__half2*)(l + idx + 2) = __halves2half2(l2, l3);
    }
}

__global__ void round_kernel(const float4* __restrict__ s, fp16* __restrict__ o, int n4)
{
    int i = blockIdx.x * blockDim.x + threadIdx.x;
    if (i < n4) {
        float4 v = s[i];
        size_t idx = (size_t)i * 4;
        *(__half2*)(o + idx)     = __halves2half2(__float2half_rn(v.x), __float2half_rn(v.y));
        *(__half2*)(o + idx + 2) = __halves2half2(__float2half_rn(v.z), __float2half_rn(v.w));
    }
}

// transpose + round: src [R,C] fp32 -> dst [C,R] fp16
__global__ void tround_kernel(const float* __restrict__ s, fp16* __restrict__ o,
                              int R, int C)
{
    __shared__ float t[32][33];
    const int bx = blockIdx.x * 32;   // C offset
    const int by = blockIdx.y * 32;   // R offset
    const int x = threadIdx.x, y = threadIdx.y;
#pragma unroll
    for (int i = 0; i < 4; i++)
        t[y + i * 8][x] = s[(size_t)(by + y + i * 8) * C + bx + x];
    __syncthreads();
#pragma unroll
    for (int i = 0; i < 4; i++)
        o[(size_t)(bx + y + i * 8) * R + by + x] = __float2half_rn(t[x][y + i * 8]);
}

__global__ void fill0_kernel(float4* __restrict__ p, int n4)
{
    int i = blockIdx.x * blockDim.x + threadIdx.x;
    if (i < n4) p[i] = make_float4(0.f, 0.f, 0.f, 0.f);
}

// ---------------------------------------------------------------------------
extern "C" void kernel_launch(void* const* d_in, const int* in_sizes, int n_in,
                              void* d_out, int out_size)
{
    const float* x    = (const float*)d_in[0];
    const float* bvec = (const float*)d_in[1];
    const float* W1   = (const float*)d_in[2];
    const float* b1   = (const float*)d_in[3];
    const float* W2   = (const float*)d_in[4];
    const float* b2   = (const float*)d_in[5];
    const float* W3   = (const float*)d_in[6];
    const float* b3   = (const float*)d_in[7];
    const float* A    = (const float*)d_in[8];
    const float* leta = (const float*)d_in[9];
    const float* ltau = (const float*)d_in[10];
    const float* Psi  = (const float*)d_in[11];
    const float* Mmat = (const float*)d_in[12];

    float* out     = (float*)d_out;
    float* o_ybg   = out;
    float* o_z     = o_ybg   + (size_t)BATCH * NOUTD;
    float* o_alpha = o_z     + (size_t)BATCH * MMDIM;
    float* o_yhat  = o_alpha + (size_t)BATCH * NCODE;

#define SYM(p, s) void* p##_; cudaGetSymbolAddress(&p##_, s); auto* p = (decltype(&s[0]))p##_
    SYM(vbuf, g_v);  SYM(abuf, g_a0);
    SYM(xsh, g_xsh); SYM(xsl, g_xsl);
    SYM(h1h, g_h1h); SYM(h1l, g_h1l);
    SYM(h2h, g_h2h); SYM(h2l, g_h2l);
    SYM(ybh, g_ybh); SYM(ybl, g_ybl);
    SYM(vh, g_vh);   SYM(vl, g_vl);
    SYM(rh, g_rh);   SYM(rl, g_rl);
    SYM(aph, g_aph); SYM(apl, g_apl);
    SYM(w1, g_w1);   SYM(w2, g_w2);   SYM(w3, g_w3);
    SYM(m, g_m);     SYM(aa, g_aa);   SYM(at, g_at);   SYM(ps, g_ps);
#undef SYM

    cudaFuncSetAttribute((void*)wgemm<EPI_GELU>,  cudaFuncAttributeMaxDynamicSharedMemorySize, SMEM_BYTES);
    cudaFuncSetAttribute((void*)wgemm<EPI_YBG>,   cudaFuncAttributeMaxDynamicSharedMemorySize, SMEM_BYTES);
    cudaFuncSetAttribute((void*)wgemm<EPI_ZSUB>,  cudaFuncAttributeMaxDynamicSharedMemorySize, SMEM_BYTES);
    cudaFuncSetAttribute((void*)wgemm<EPI_RSUB>,  cudaFuncAttributeMaxDynamicSharedMemorySize, SMEM_BYTES);
    cudaFuncSetAttribute((void*)wgemm<EPI_FISTA>, cudaFuncAttributeMaxDynamicSharedMemorySize, SMEM_BYTES);
    cudaFuncSetAttribute((void*)wgemm<EPI_ADD>,   cudaFuncAttributeMaxDynamicSharedMemorySize, SMEM_BYTES);

    // host-side FISTA momentum (data-independent)
    float betas[KSTEPS + 1];
    {
        float t = 1.0f; betas[0] = 0.0f;
        for (int k = 1; k <= KSTEPS; k++) {
            float tn = 0.5f * (1.0f + sqrtf(1.0f + 4.0f * t * t));
            betas[k] = (t - 1.0f) / tn;
            t = tn;
        }
    }

    // ---- prep -----------------------------------------------------------------
    {
        int n4 = (BATCH * PDIM) / 4;
        split_kernel<<<(n4 + 255) / 256, 256>>>((const float4*)x, xsh, xsl, n4);
    }
    auto rounds = [&](const float* s, fp16* o, size_t n) {
        int n4 = (int)(n / 4);
        round_kernel<<<(n4 + 255) / 256, 256>>>((const float4*)s, o, n4);
    };
    rounds(A,    aa, (size_t)MMDIM * NCODE);
    rounds(Mmat, m,  (size_t)MMDIM * NOUTD);
    rounds(Psi,  ps, (size_t)NOUTD * NCODE);
    tround_kernel<<<dim3(H1DIM / 32, PDIM / 32),  dim3(32, 8)>>>(W1, w1, PDIM,  H1DIM);
    tround_kernel<<<dim3(H2DIM / 32, H1DIM / 32), dim3(32, 8)>>>(W2, w2, H1DIM, H2DIM);
    tround_kernel<<<dim3(NOUTD / 32, H2DIM / 32), dim3(32, 8)>>>(W3, w3, H2DIM, NOUTD);
    tround_kernel<<<dim3(NCODE / 32, MMDIM / 32), dim3(32, 8)>>>(A,  at, MMDIM, NCODE);

    const int nA = BATCH * NCODE;
    fill0_kernel<<<(nA / 4 + 255) / 256, 256>>>((float4*)vbuf, nA / 4);
    fill0_kernel<<<(nA / 4 + 255) / 256, 256>>>((float4*)abuf, nA / 4);
    fill0_kernel<<<(nA / 8 + 255) / 256, 256>>>((float4*)vh, nA / 8);
    fill0_kernel<<<(nA / 8 + 255) / 256, 256>>>((float4*)vl, nA / 8);

    const dim3 blk(256);
#define GRID(N) dim3((N) / 128, BATCH / 128)

    // ---- background MLP -----------------------------------------------------
    wgemm<EPI_GELU><<<GRID(H1DIM), blk, SMEM_BYTES>>>(
        xsh, xsl, w1, H1DIM, PDIM, nullptr, h1h, h1l,
        b1, nullptr, nullptr, nullptr, nullptr, nullptr, nullptr, 0, 0.f);
    wgemm<EPI_GELU><<<GRID(H2DIM), blk, SMEM_BYTES>>>(
        h1h, h1l, w2, H2DIM, H1DIM, nullptr, h2h, h2l,
        b2, nullptr, nullptr, nullptr, nullptr, nullptr, nullptr, 0, 0.f);
    wgemm<EPI_YBG><<<GRID(NOUTD), blk, SMEM_BYTES>>>(
        h2h, h2l, w3, NOUTD, H2DIM, o_ybg, ybh, ybl,
        b3, nullptr, nullptr, nullptr, nullptr, nullptr, nullptr, 0, 0.f);

    // ---- z = b - y_bg @ M^T --------------------------------------------------
    wgemm<EPI_ZSUB><<<GRID(MMDIM), blk, SMEM_BYTES>>>(
        ybh, ybl, m, MMDIM, NOUTD, o_z, nullptr, nullptr,
        bvec, nullptr, nullptr, nullptr, nullptr, nullptr, nullptr, 0, 0.f);

    // ---- FISTA loop (v-momentum fused into EPI_FISTA epilogue) ---------------
    for (int k = 0; k < KSTEPS; k++) {
        // r = v @ A^T - z  (fp16 hi/lo out)
        wgemm<EPI_RSUB><<<GRID(MMDIM), blk, SMEM_BYTES>>>(
            vh, vl, aa, MMDIM, NCODE, nullptr, rh, rl,
            o_z, nullptr, nullptr, nullptr, nullptr, nullptr, nullptr, 0, 0.f);
        // alpha_new = soft(v - eta*(r @ A), eta*tau);  v_next fused
        if (k < KSTEPS - 1) {
            wgemm<EPI_FISTA><<<GRID(NCODE), blk, SMEM_BYTES>>>(
                rh, rl, at, NCODE, MMDIM, abuf, nullptr, nullptr,
                vbuf, abuf, vbuf, vh, vl, leta, ltau, k, betas[k + 1]);
        } else {
            wgemm<EPI_FISTA><<<GRID(NCODE), blk, SMEM_BYTES>>>(
                rh, rl, at, NCODE, MMDIM, o_alpha, aph, apl,
                vbuf, abuf, nullptr, nullptr, nullptr, leta, ltau, k, 0.f);
        }
    }

    // ---- y_hat = y_bg + alpha @ Psi^T ----------------------------------------
    wgemm<EPI_ADD><<<GRID(NOUTD), blk, SMEM_BYTES>>>(
        aph, apl, ps, NOUTD, NCODE, o_yhat, nullptr, nullptr,
        o_ybg, nullptr, nullptr, nullptr, nullptr, nullptr, nullptr, 0, 0.f);
}